// round 17
// baseline (speedup 1.0000x reference)
#include <cuda_runtime.h>
#include <cuda_bf16.h>
#include <cstdint>
#include <cstddef>

#define S_  2048
#define D_  64
#define H_  16
#define B_  2
#define BH_ 32
#define TQ  128
#define TK  128
#define NKT (S_/TK)      /* 16 */

// ---------------- device scratch (allocation-free rule) ----------------
__device__ __nv_bfloat16 g_qhi[BH_*S_*D_], g_qlo[BH_*S_*D_];
__device__ __nv_bfloat16 g_khi[BH_*S_*D_], g_klo[BH_*S_*D_];
__device__ __nv_bfloat16 g_vthi[BH_*D_*S_], g_vtlo[BH_*D_*S_];   // V^T: [bh][d][k]

// ---------------- helpers ----------------
__device__ __forceinline__ unsigned smem_u32(const void* p){
    unsigned a;
    asm("{ .reg .u64 t; cvta.to.shared.u64 t, %1; cvt.u32.u64 %0, t; }":"=r"(a):"l"(p));
    return a;
}
__device__ __forceinline__ void ldsm_x4(unsigned& a0,unsigned& a1,unsigned& a2,unsigned& a3, unsigned addr){
    asm volatile("ldmatrix.sync.aligned.m8n8.x4.shared.b16 {%0,%1,%2,%3}, [%4];"
        : "=r"(a0),"=r"(a1),"=r"(a2),"=r"(a3) : "r"(addr));
}
__device__ __forceinline__ void mma16816(float* c, unsigned a0,unsigned a1,unsigned a2,unsigned a3,
                                         unsigned b0,unsigned b1){
    asm volatile("mma.sync.aligned.m16n8k16.row.col.f32.bf16.bf16.f32 "
        "{%0,%1,%2,%3}, {%4,%5,%6,%7}, {%8,%9}, {%0,%1,%2,%3};"
        : "+f"(c[0]),"+f"(c[1]),"+f"(c[2]),"+f"(c[3])
        : "r"(a0),"r"(a1),"r"(a2),"r"(a3),"r"(b0),"r"(b1));
}
__device__ __forceinline__ void cp16(unsigned saddr, const void* g){
    asm volatile("cp.async.cg.shared.global [%0], [%1], 16;" :: "r"(saddr), "l"(g));
}
#define CP_COMMIT() asm volatile("cp.async.commit_group;" ::: "memory")
#define CP_WAIT(n)  asm volatile("cp.async.wait_group %0;" :: "n"(n) : "memory")

// pack two floats -> bf16x2 hi and bf16x2 lo-residual
__device__ __forceinline__ void hilo2(float a, float b, unsigned& h, unsigned& lo){
    __nv_bfloat16 ha = __float2bfloat16(a), hb = __float2bfloat16(b);
    h  = ((unsigned)__bfloat16_as_ushort(hb) << 16) | (unsigned)__bfloat16_as_ushort(ha);
    __nv_bfloat16 la = __float2bfloat16(a - __bfloat162float(ha));
    __nv_bfloat16 lb = __float2bfloat16(b - __bfloat162float(hb));
    lo = ((unsigned)__bfloat16_as_ushort(lb) << 16) | (unsigned)__bfloat16_as_ushort(la);
}

// ---------------- prep: Q,K elementwise hi/lo; V transpose hi/lo ----------------
__global__ __launch_bounds__(256) void prep_kernel(
    const float* __restrict__ Q, const float* __restrict__ K, const float* __restrict__ V)
{
    const int tid = threadIdx.x, bh = blockIdx.y, z = blockIdx.z;
    if (z < 2){
        const float* src = z ? K : Q;
        __nv_bfloat16* dh = z ? g_khi : g_qhi;
        __nv_bfloat16* dl = z ? g_klo : g_qlo;
        size_t base = ((size_t)bh*S_ + blockIdx.x*64)*D_;
        #pragma unroll
        for (int it = 0; it < 8; ++it){
            int i2 = it*256 + tid;
            float2 v = *(const float2*)(src + base + i2*2);
            __nv_bfloat16 h0 = __float2bfloat16(v.x), h1 = __float2bfloat16(v.y);
            __nv_bfloat162 hh; hh.x = h0; hh.y = h1;
            __nv_bfloat162 ll;
            ll.x = __float2bfloat16(v.x - __bfloat162float(h0));
            ll.y = __float2bfloat16(v.y - __bfloat162float(h1));
            *(__nv_bfloat162*)(dh + base + i2*2) = hh;
            *(__nv_bfloat162*)(dl + base + i2*2) = ll;
        }
    } else {
        __shared__ float ts[64][69];
        const int k0 = blockIdx.x * 64;
        #pragma unroll
        for (int it = 0; it < 16; ++it){
            int lin = it*256 + tid;
            int kk = lin >> 6, d = lin & 63;
            ts[kk][d] = V[((size_t)bh*S_ + k0 + kk)*D_ + d];
        }
        __syncthreads();
        #pragma unroll
        for (int it = 0; it < 16; ++it){
            int lin = it*256 + tid;
            int d = lin >> 6, kk = lin & 63;
            float v = ts[kk][d];
            __nv_bfloat16 h = __float2bfloat16(v);
            __nv_bfloat16 l = __float2bfloat16(v - __bfloat162float(h));
            size_t o = ((size_t)bh*D_ + d)*S_ + k0 + kk;
            g_vthi[o] = h;
            g_vtlo[o] = l;
        }
    }
}

// ---------------- fused attention ----------------
// K rows: 64 elems stride SQ1=72 (144B). V^T rows: 128 elems stride SV=136 (272B).
// Double-buffered K/V; Q lives in registers after a one-time staged load.
#define SQ1   72
#define SV    136
#define O_KH  0
#define O_KL  18432
#define O_VH  36864
#define O_VL  54272
#define BUFSZ 71680
#define F_QH  BUFSZ              /* Q staged in buffer 1 before the loop */
#define F_QL  (BUFSZ + 18432)
#define F_IL  (2*BUFSZ)          /* 143360 */
#define SMEMF (2*BUFSZ + 512)    /* 143872 */

__global__ __launch_bounds__(256) void fused_attn_kernel(
    const unsigned* __restrict__ mask, const float* __restrict__ adj,
    float* __restrict__ P, float* __restrict__ Out)
{
    extern __shared__ char smem[];
    const unsigned sb = smem_u32(smem);
    const int tid = threadIdx.x, w = tid >> 5, l = tid & 31;
    const int bh = blockIdx.y, b = bh >> 4;
    const int q0 = blockIdx.x * TQ;

    const __nv_bfloat16* kh_g = g_khi + (size_t)bh*S_*D_;
    const __nv_bfloat16* kl_g = g_klo + (size_t)bh*S_*D_;
    const __nv_bfloat16* vh_g = g_vthi + (size_t)bh*D_*S_;
    const __nv_bfloat16* vl_g = g_vtlo + (size_t)bh*D_*S_;

    // prologue: stage Q hi/lo (buf1 area) + tile0 K/V (buf0), one group
    {
        const __nv_bfloat16* qh = g_qhi + ((size_t)bh*S_ + q0)*D_;
        const __nv_bfloat16* ql = g_qlo + ((size_t)bh*S_ + q0)*D_;
        #pragma unroll
        for (int it = 0; it < 8; ++it){
            int lin = it*256 + tid;
            int half = lin >> 10, idx = lin & 1023;
            int row = idx >> 3, g = idx & 7;
            cp16(sb + (half ? F_QL : F_QH) + (row*SQ1 + g*8)*2,
                 (half ? ql : qh) + row*D_ + g*8);
        }
        #pragma unroll
        for (int it = 0; it < 16; ++it){
            int lin = it*256 + tid;
            int sel = lin >> 10, idx = lin & 1023;
            if (sel < 2){   // K hi/lo
                int row = idx >> 3, g = idx & 7;
                cp16(sb + (sel ? O_KL : O_KH) + (row*SQ1 + g*8)*2,
                     (sel ? kl_g : kh_g) + (size_t)row*D_ + g*8);
            } else {        // V hi/lo
                int row = idx >> 4, g = idx & 15;
                cp16(sb + (sel == 3 ? O_VL : O_VH) + (row*SV + g*8)*2,
                     (sel == 3 ? vl_g : vh_g) + (size_t)row*S_ + g*8);
            }
        }
        CP_COMMIT(); CP_WAIT(0);
        __syncthreads();
    }

    // lane constants
    const int la_row = 16*w + (l & 15);
    const int la_k8  = (l >> 4) * 8;
    const int r8  = 8*((l >> 4) & 1);     // x4 B-load: row-half select
    const int k8  = 8*((l >> 3) & 1);     // x4 B-load: k-half select
    const int r7  = l & 7;
    const int qr  = l >> 2;
    const int ci  = l & 3;

    // Q fragments -> registers (persist across all tiles)
    unsigned qfh[4][4], qfl[4][4];
    #pragma unroll
    for (int kk = 0; kk < 4; ++kk){
        unsigned adr = (la_row*SQ1 + kk*16 + la_k8)*2;
        ldsm_x4(qfh[kk][0],qfh[kk][1],qfh[kk][2],qfh[kk][3], sb + F_QH + adr);
        ldsm_x4(qfl[kk][0],qfl[kk][1],qfl[kk][2],qfl[kk][3], sb + F_QL + adr);
    }
    __syncthreads();   // all Q frag reads done before buf1 is refilled

    float l_run[2] = {0.f, 0.f};
    float oacc[8][4];
    #pragma unroll
    for (int dg = 0; dg < 8; ++dg)
        #pragma unroll
        for (int j = 0; j < 4; ++j) oacc[dg][j] = 0.f;

    for (int kt = 0; kt < NKT; ++kt){
        const int k0 = kt * TK;
        if (kt + 1 < NKT){
            const unsigned bufn = sb + ((kt+1)&1)*BUFSZ;
            const int kn = k0 + TK;
            #pragma unroll
            for (int it = 0; it < 16; ++it){
                int lin = it*256 + tid;
                int sel = lin >> 10, idx = lin & 1023;
                if (sel < 2){
                    int row = idx >> 3, g = idx & 7;
                    cp16(bufn + (sel ? O_KL : O_KH) + (row*SQ1 + g*8)*2,
                         (sel ? kl_g : kh_g) + (size_t)(kn + row)*D_ + g*8);
                } else {
                    int row = idx >> 4, g = idx & 15;
                    cp16(bufn + (sel == 3 ? O_VL : O_VH) + (row*SV + g*8)*2,
                         (sel == 3 ? vl_g : vh_g) + (size_t)row*S_ + kn + g*8);
                }
            }
            CP_COMMIT();
            CP_WAIT(1);
        } else {
            CP_WAIT(0);
        }
        __syncthreads();

        const unsigned buf = sb + (kt&1)*BUFSZ;

        // ---- QK^T: acc[16][4], K loaded 2 n-tiles per ldsm_x4 ----
        float acc[16][4];
        #pragma unroll
        for (int nt = 0; nt < 16; ++nt)
            #pragma unroll
            for (int j = 0; j < 4; ++j) acc[nt][j] = 0.f;

        #pragma unroll
        for (int kk = 0; kk < 4; ++kk){
            #pragma unroll
            for (int nt2 = 0; nt2 < 8; ++nt2){
                unsigned adr = ((16*nt2 + r7 + r8)*SQ1 + kk*16 + k8)*2;
                unsigned b0,b1,b2,b3, c0,c1,c2,c3;
                ldsm_x4(b0,b1,b2,b3, buf + O_KH + adr);
                ldsm_x4(c0,c1,c2,c3, buf + O_KL + adr);
                mma16816(acc[2*nt2],   qfh[kk][0],qfh[kk][1],qfh[kk][2],qfh[kk][3], b0,b1);
                mma16816(acc[2*nt2+1], qfh[kk][0],qfh[kk][1],qfh[kk][2],qfh[kk][3], b2,b3);
                mma16816(acc[2*nt2],   qfh[kk][0],qfh[kk][1],qfh[kk][2],qfh[kk][3], c0,c1);
                mma16816(acc[2*nt2+1], qfh[kk][0],qfh[kk][1],qfh[kk][2],qfh[kk][3], c2,c3);
                mma16816(acc[2*nt2],   qfl[kk][0],qfl[kk][1],qfl[kk][2],qfl[kk][3], b0,b1);
                mma16816(acc[2*nt2+1], qfl[kk][0],qfl[kk][1],qfl[kk][2],qfl[kk][3], b2,b3);
            }
        }

        // ---- epilogue in place: acc <- u = exp((acc+adj)/8), masked->0 ----
        #pragma unroll
        for (int h = 0; h < 2; ++h){
            const int row = 16*w + qr + 8*h;
            const float2* ap = (const float2*)(adj + ((size_t)bh*S_ + q0 + row)*S_ + k0);
            const uint2*  mp = (const uint2*) (mask + ((size_t)b*S_  + q0 + row)*S_ + k0);
            float2*       pp = (float2*)(P + ((size_t)bh*S_ + q0 + row)*S_ + k0);
            float es = 0.f;
            #pragma unroll
            for (int nt = 0; nt < 16; ++nt){
                float2 a = ap[ci + 4*nt];
                uint2 mv = mp[ci + 4*nt];
                float x0 = __expf((acc[nt][2*h]   + a.x) * 0.125f);
                float x1 = __expf((acc[nt][2*h+1] + a.y) * 0.125f);
                if (mv.x) x0 = 0.f;
                if (mv.y) x1 = 0.f;
                acc[nt][2*h] = x0; acc[nt][2*h+1] = x1;
                es += x0 + x1;
                pp[ci + 4*nt] = make_float2(x0, x1);
            }
            es += __shfl_xor_sync(0xffffffffu, es, 1);
            es += __shfl_xor_sync(0xffffffffu, es, 2);
            l_run[h] += es;
        }

        // ---- PV: O += u @ V, V loaded 2 d-tiles per ldsm_x4 ----
        #pragma unroll
        for (int kb = 0; kb < 8; ++kb){
            unsigned a0,a1,a2,a3, b0,b1,b2,b3;
            hilo2(acc[2*kb][0],   acc[2*kb][1],   a0, b0);
            hilo2(acc[2*kb][2],   acc[2*kb][3],   a1, b1);
            hilo2(acc[2*kb+1][0], acc[2*kb+1][1], a2, b2);
            hilo2(acc[2*kb+1][2], acc[2*kb+1][3], a3, b3);
            #pragma unroll
            for (int dg2 = 0; dg2 < 4; ++dg2){
                unsigned adr = ((16*dg2 + r7 + r8)*SV + kb*16 + k8)*2;
                unsigned vh0,vh1,vh2,vh3, vl0,vl1,vl2,vl3;
                ldsm_x4(vh0,vh1,vh2,vh3, buf + O_VH + adr);
                ldsm_x4(vl0,vl1,vl2,vl3, buf + O_VL + adr);
                mma16816(oacc[2*dg2],   a0,a1,a2,a3, vh0,vh1);
                mma16816(oacc[2*dg2+1], a0,a1,a2,a3, vh2,vh3);
                mma16816(oacc[2*dg2],   a0,a1,a2,a3, vl0,vl1);
                mma16816(oacc[2*dg2+1], a0,a1,a2,a3, vl2,vl3);
                mma16816(oacc[2*dg2],   b0,b1,b2,b3, vh0,vh1);
                mma16816(oacc[2*dg2+1], b0,b1,b2,b3, vh2,vh3);
            }
        }
        __syncthreads();   // all reads of buf done before it is refilled
    }

    // ---- write O = oacc / l ----
    #pragma unroll
    for (int h = 0; h < 2; ++h){
        const int row = 16*w + qr + 8*h;
        const float inv = 1.0f / l_run[h];
        float2* op = (float2*)(Out + ((size_t)bh*S_ + q0 + row)*D_);
        #pragma unroll
        for (int dg = 0; dg < 8; ++dg)
            op[ci + 4*dg] = make_float2(oacc[dg][2*h]*inv, oacc[dg][2*h+1]*inv);
    }

    // ---- publish 1/l, then scale this CTA's P stripe in place ----
    float* sm_il = (float*)(smem + F_IL);
    if (ci == 0){
        #pragma unroll
        for (int h = 0; h < 2; ++h){
            const int row = 16*w + qr + 8*h;
            sm_il[row] = 1.0f / l_run[h];
        }
    }
    __syncthreads();

    #pragma unroll
    for (int j = 0; j < 16; ++j){
        const int lr = 8*j + w;              // 0..127
        const float il = sm_il[lr];
        float4* pr = (float4*)(P + ((size_t)bh*S_ + q0 + lr)*S_);
        #pragma unroll 4
        for (int c = 0; c < 16; ++c){
            int idx = c*32 + l;              // 512 float4 across the row
            float4 v = pr[idx];
            v.x *= il; v.y *= il; v.z *= il; v.w *= il;
            pr[idx] = v;
        }
    }
}

// ---------------------------------------------------------------------------
extern "C" void kernel_launch(void* const* d_in, const int* in_sizes, int n_in,
                              void* d_out, int out_size) {
    const float*    Q    = (const float*)d_in[0];
    const float*    K    = (const float*)d_in[1];
    const float*    V    = (const float*)d_in[2];
    const unsigned* mask = (const unsigned*)d_in[3];
    const float*    adj  = (const float*)d_in[4];

    float* out = (float*)d_out;                       // (B,H,S,D)
    float* P   = out + (size_t)B_ * H_ * S_ * D_;     // (B,H,S,S)

    cudaFuncSetAttribute(fused_attn_kernel, cudaFuncAttributeMaxDynamicSharedMemorySize, SMEMF);

    prep_kernel<<<dim3(S_/64, BH_, 3), 256>>>(Q, K, V);
    fused_attn_kernel<<<dim3(S_/TQ, BH_), 256, SMEMF>>>(mask, adj, P, out);
}